// round 12
// baseline (speedup 1.0000x reference)
#include <cuda_runtime.h>
#include <math.h>

// PINN beam fields: Taylor-jet table (129 nodes) + nearest-node Taylor eval.
// R11: PDL overlap — eval_tab launches concurrently with build_tab
// (ProgrammaticStreamSerialization); eval prefetches x and ramps CTAs, then
// griddepcontrol.wait gates only the table read.
// build_tab: 32 lanes per node, MUFU tanh, u-jet order 2, w-jet order 4,
//            stored pre-scaled (U_k = u^(k) h^k/k!, W_k = w^(k) h^k/k!).
// eval_tab:  4.2KB jet table in SMEM; 2 points/thread, float2 I/O, 512x512;
//            per point TWO LDS.128, Horner in t = z*128 - rn(z*128).

#define EA_C 1.0e4f
#define EI_C 1.0e2f
#define NODES 128
#define NNODES (NODES + 1)
#define FNODES 128.0f
#define FN2 16384.0f           // NODES^2
#define FN3 2097152.0f         // NODES^3
#define TWO_LOG2E 2.8853900817779268f   // 2/ln(2)

// plane A: (U0, U1, U2, W4) ; plane B: (W0, W1, W2, W3)
__device__ float4 g_tabA[NNODES];
__device__ float4 g_tabB[NNODES];

// tanh + sech^2 via MUFU, no cancellation near saturation:
// e = e^{2a}; q = 2/(e+1); t = 1-q; s = q^2 e
__device__ __forceinline__ void tanh_pair(float a, float& t, float& s) {
    float p = a * TWO_LOG2E;
    float e;
    asm("ex2.approx.f32 %0, %1;" : "=f"(e) : "f"(p));
    float d = e + 1.0f;
    float r;
    asm("rcp.approx.f32 %0, %1;" : "=f"(r) : "f"(d));
    float q = r + r;
    t = 1.0f - q;
    s = q * q * e;
}

// ------------------------- Kernel A: build table -------------------------
// gtid/32 = node; lane = gtid%32. neuron j = lane%16, k-half = lane/16.
__global__ __launch_bounds__(256) void build_tab(
    const float* __restrict__ W1, const float* __restrict__ b1,
    const float* __restrict__ W2, const float* __restrict__ b2,
    const float* __restrict__ W3, const float* __restrict__ b3)
{
    int gtid = blockIdx.x * blockDim.x + threadIdx.x;
    int grp  = gtid >> 5;
    int lane = gtid & 31;
    int j    = lane & 15;            // output neuron
    int khalf = lane >> 4;           // 0: k in [0,8), 1: k in [8,16)
    int node = grp < NNODES ? grp : (NNODES - 1);   // clamp, keep warp uniform
    bool writer = (lane == 0) && (grp < NNODES);

    const float hstep = 1.0f / FNODES;
    float z = (float)node * hstep;

    // tanh derivative chain: f1=s; f2=-2ts; f3=2s(2t^2-s); f4=8ts(2s-t^2)

    // ---- layer 1 jets for this lane's 8 k's; fused partial k-sum ----
    int k0 = khalf * 8;
    float g0 = 0.f, g1 = 0.f, g2 = 0.f, g3 = 0.f, g4 = 0.f;
#pragma unroll
    for (int m = 0; m < 8; m++) {
        int k = k0 + m;
        float w1k = W1[k];
        float a0  = fmaf(w1k, z, b1[k]);
        float t, s;
        tanh_pair(a0, t, s);
        float t2 = t * t;
        float f2 = -2.0f * t * s;
        float f3 = 2.0f * s * fmaf(2.0f, t2, -s);
        float f4 = 8.0f * t * s * fmaf(-1.0f, t2, 2.0f * s);
        float wsq = w1k * w1k;

        float w = W2[j * 16 + k];
        g0 = fmaf(w, t, g0);
        g1 = fmaf(w, s * w1k, g1);
        g2 = fmaf(w, f2 * wsq, g2);
        g3 = fmaf(w, f3 * wsq * w1k, g3);
        g4 = fmaf(w, f4 * wsq * wsq, g4);
    }

    // combine the two k-halves (lanes j and j+16 hold the halves)
    g0 += __shfl_xor_sync(0xffffffffu, g0, 16);
    g1 += __shfl_xor_sync(0xffffffffu, g1, 16);
    g2 += __shfl_xor_sync(0xffffffffu, g2, 16);
    g3 += __shfl_xor_sync(0xffffffffu, g3, 16);
    g4 += __shfl_xor_sync(0xffffffffu, g4, 16);
    g0 += b2[j];

    // ---- layer 2 tanh jets + layer 3 partials (duplicated across k-half
    //      lanes; halved by 0.5f before the full-warp reduce) ----
    float t, s;
    tanh_pair(g0, t, s);
    float t2 = t * t;
    float f2 = -2.0f * t * s;
    float f3 = 2.0f * s * fmaf(2.0f, t2, -s);
    float f4 = 8.0f * t * s * fmaf(-1.0f, t2, 2.0f * s);

    float g1sq = g1 * g1;
    float y1 = s * g1;
    float y2 = fmaf(s, g2, f2 * g1sq);
    float y3 = fmaf(s, g3, fmaf(3.0f * f2 * g1, g2, f3 * g1sq * g1));
    float y4 = fmaf(s, g4,
               fmaf(f2, fmaf(4.0f * g1, g3, 3.0f * g2 * g2),
               fmaf(6.0f * f3 * g1sq, g2, f4 * g1sq * g1sq)));

    float wu = 0.5f * W3[j];
    float ww = 0.5f * W3[16 + j];
    float u0 = wu * t,  u1 = wu * y1, u2 = wu * y2;
    float w0 = ww * t,  w1 = ww * y1;
    float w2a = ww * y2, w3a = ww * y3, w4a = ww * y4;

#define RED32(v) v += __shfl_xor_sync(0xffffffffu, v, 1); \
                 v += __shfl_xor_sync(0xffffffffu, v, 2); \
                 v += __shfl_xor_sync(0xffffffffu, v, 4); \
                 v += __shfl_xor_sync(0xffffffffu, v, 8); \
                 v += __shfl_xor_sync(0xffffffffu, v, 16);
    RED32(u0) RED32(u1) RED32(u2)
    RED32(w0) RED32(w1) RED32(w2a) RED32(w3a) RED32(w4a)
#undef RED32

    if (writer) {
        u0 += b3[0];
        w0 += b3[1];
        const float h1f = hstep;
        const float h2f = hstep * hstep * 0.5f;
        const float h3f = hstep * hstep * hstep * (1.0f / 6.0f);
        const float h4f = hstep * hstep * hstep * hstep * (1.0f / 24.0f);
        g_tabA[node] = make_float4(u0, u1 * h1f, u2 * h2f, w4a * h4f);
        g_tabB[node] = make_float4(w0, w1 * h1f, w2a * h2f, w3a * h3f);
    }

    // PDL: signal dependents once this CTA's table writes are done.
    asm volatile("griddepcontrol.launch_dependents;" ::: "memory");
}

// ------------------------- Kernel B: evaluate -------------------------
__device__ __forceinline__ void eval_point(
    const float4* __restrict__ sA, const float4* __restrict__ sB, float z,
    float& u, float& w, float& wx, float& Nf, float& Mf, float& Qf)
{
    float f = z * FNODES;                       // exact (power-of-2 scale)
    int idx = __float2int_rn(f);
    idx = idx < 0 ? 0 : (idx > NODES ? NODES : idx);
    float t = f - (float)idx;                   // exact, in [-1/2, 1/2]

    float4 A = sA[idx];    // (U0, U1, U2, W4)
    float4 B = sB[idx];    // (W0, W1, W2, W3)

    // u = U0 + U1 t + U2 t^2
    u  = fmaf(t, fmaf(t, A.z, A.y), A.x);
    // u' = NODES (U1 + 2U2 t)
    float up = FNODES * fmaf(t, A.z + A.z, A.y);
    // w = W0 + W1 t + W2 t^2 + W3 t^3 + W4 t^4
    w  = fmaf(t, fmaf(t, fmaf(t, fmaf(t, A.w, B.w), B.z), B.y), B.x);
    // w' = NODES (W1 + 2W2 t + 3W3 t^2 + 4W4 t^3)
    wx = FNODES * fmaf(t, fmaf(t, fmaf(t, 4.0f * A.w, 3.0f * B.w), B.z + B.z), B.y);
    // w'' = NODES^2 (2W2 + 6W3 t + 12W4 t^2)
    float wpp = FN2 * fmaf(t, fmaf(t, 12.0f * A.w, 6.0f * B.w), B.z + B.z);
    // w''' = NODES^3 (6W3 + 24W4 t)
    float wppp = FN3 * fmaf(t, 24.0f * A.w, 6.0f * B.w);

    Nf = EA_C * fmaf(0.5f * wx, wx, up);
    Mf = -EI_C * wpp;
    Qf = fmaf(Nf, wx, -EI_C * wppp);
}

__global__ __launch_bounds__(512) void eval_tab(
    const float* __restrict__ x, float* __restrict__ out, int n)
{
    __shared__ float4 sA[NNODES];   // 2,064 B
    __shared__ float4 sB[NNODES];   // 2,064 B

    int n2 = n >> 1;
    int q = blockIdx.x * blockDim.x + threadIdx.x;

    // Prefetch x BEFORE waiting on the producer grid: the LDG flies while
    // build_tab is still finishing.
    float2 xs = make_float2(0.f, 0.f);
    bool valid = q < n2;
    const float2* x2 = reinterpret_cast<const float2*>(x);
    if (valid) xs = x2[q];

    // PDL: block until build_tab's writes are visible.
    asm volatile("griddepcontrol.wait;" ::: "memory");

    if (threadIdx.x < NNODES) {
        sA[threadIdx.x] = g_tabA[threadIdx.x];
        sB[threadIdx.x] = g_tabB[threadIdx.x];
    }
    __syncthreads();

    if (!valid) return;

    float2 ru, rw, rwx, rN, rM, rQ;
    eval_point(sA, sB, xs.x, ru.x, rw.x, rwx.x, rN.x, rM.x, rQ.x);
    eval_point(sA, sB, xs.y, ru.y, rw.y, rwx.y, rN.y, rM.y, rQ.y);

    float2* o2 = reinterpret_cast<float2*>(out);
    o2[0 * n2 + q] = ru;
    o2[1 * n2 + q] = rw;
    o2[2 * n2 + q] = rwx;
    o2[3 * n2 + q] = rN;
    o2[4 * n2 + q] = rM;
    o2[5 * n2 + q] = rQ;
}

extern "C" void kernel_launch(void* const* d_in, const int* in_sizes, int n_in,
                              void* d_out, int out_size)
{
    const float* x  = (const float*)d_in[0];
    const float* W1 = (const float*)d_in[1];
    const float* b1 = (const float*)d_in[2];
    const float* W2 = (const float*)d_in[3];
    const float* b2 = (const float*)d_in[4];
    const float* W3 = (const float*)d_in[5];
    const float* b3 = (const float*)d_in[6];
    float* out = (float*)d_out;
    int n = in_sizes[0];

    int bthreads = 32 * NNODES;                      // 4128
    build_tab<<<(bthreads + 255) / 256, 256>>>(W1, b1, W2, b2, W3, b3);

    // eval_tab with Programmatic Stream Serialization (PDL overlap)
    int n2 = n >> 1;
    int grid = (n2 + 511) / 512;                     // 512 for n = 524288

    cudaLaunchConfig_t cfg = {};
    cfg.gridDim  = dim3((unsigned)grid, 1, 1);
    cfg.blockDim = dim3(512, 1, 1);
    cfg.dynamicSmemBytes = 0;
    cfg.stream = 0;
    cudaLaunchAttribute attrs[1];
    attrs[0].id = cudaLaunchAttributeProgrammaticStreamSerialization;
    attrs[0].val.programmaticStreamSerializationAllowed = 1;
    cfg.attrs = attrs;
    cfg.numAttrs = 1;
    cudaLaunchKernelEx(&cfg, eval_tab, x, out, n);
}

// round 13
// speedup vs baseline: 1.0239x; 1.0239x over previous
#include <cuda_runtime.h>
#include <math.h>

// PINN beam fields, SINGLE fused kernel:
//   phase 1: CTAs 0..128 (warp 0) build a 129-node Taylor-jet table
//            (u-jet order 2, w-jet order 4, pre-scaled U_k = u^(k) h^k/k!).
//   barrier: self-resetting global ticket barrier (monotonic counter, works
//            across CUDA-graph replays; co-residency guaranteed by
//            __launch_bounds__(512,3) on a 444-CTA grid = 3/SM x 148).
//   phase 2: all CTAs copy the 4.1KB table to SMEM and evaluate 2 points per
//            thread (float2 I/O, 2x LDS.128 per point, Horner in
//            t = z*128 - rn(z*128) in [-1/2, 1/2]).

#define EA_C 1.0e4f
#define EI_C 1.0e2f
#define NODES 128
#define NNODES (NODES + 1)
#define FNODES 128.0f
#define FN2 16384.0f           // NODES^2
#define FN3 2097152.0f         // NODES^3
#define TWO_LOG2E 2.8853900817779268f   // 2/ln(2)
#define GRID_CTAS 444
#define CTA_THREADS 512

// plane A: (U0, U1, U2, W4) ; plane B: (W0, W1, W2, W3)
__device__ float4 g_tabA[NNODES];
__device__ float4 g_tabB[NNODES];
__device__ unsigned int g_ticket;   // monotonic barrier counter (never reset)

// tanh + sech^2 via MUFU, no cancellation near saturation:
// e = e^{2a}; q = 2/(e+1); t = 1-q; s = q^2 e
__device__ __forceinline__ void tanh_pair(float a, float& t, float& s) {
    float p = a * TWO_LOG2E;
    float e;
    asm("ex2.approx.f32 %0, %1;" : "=f"(e) : "f"(p));
    float d = e + 1.0f;
    float r;
    asm("rcp.approx.f32 %0, %1;" : "=f"(r) : "f"(d));
    float q = r + r;
    t = 1.0f - q;
    s = q * q * e;
}

// Build one table node with the 32 lanes of one warp.
// lane j = lane%16 -> layer-2 neuron; khalf = lane/16 -> k in [8*khalf, 8*khalf+8)
__device__ void build_node(int node, int lane,
    const float* __restrict__ W1, const float* __restrict__ b1,
    const float* __restrict__ W2, const float* __restrict__ b2,
    const float* __restrict__ W3, const float* __restrict__ b3)
{
    int j = lane & 15;
    int khalf = lane >> 4;
    const float hstep = 1.0f / FNODES;
    float z = (float)node * hstep;

    // tanh derivative chain: f1=s; f2=-2ts; f3=2s(2t^2-s); f4=8ts(2s-t^2)
    int k0 = khalf * 8;
    float g0 = 0.f, g1 = 0.f, g2 = 0.f, g3 = 0.f, g4 = 0.f;
#pragma unroll
    for (int m = 0; m < 8; m++) {
        int k = k0 + m;
        float w1k = W1[k];
        float a0  = fmaf(w1k, z, b1[k]);
        float t, s;
        tanh_pair(a0, t, s);
        float t2 = t * t;
        float f2 = -2.0f * t * s;
        float f3 = 2.0f * s * fmaf(2.0f, t2, -s);
        float f4 = 8.0f * t * s * fmaf(-1.0f, t2, 2.0f * s);
        float wsq = w1k * w1k;

        float w = W2[j * 16 + k];
        g0 = fmaf(w, t, g0);
        g1 = fmaf(w, s * w1k, g1);
        g2 = fmaf(w, f2 * wsq, g2);
        g3 = fmaf(w, f3 * wsq * w1k, g3);
        g4 = fmaf(w, f4 * wsq * wsq, g4);
    }

    // combine the two k-halves (lanes j and j+16)
    g0 += __shfl_xor_sync(0xffffffffu, g0, 16);
    g1 += __shfl_xor_sync(0xffffffffu, g1, 16);
    g2 += __shfl_xor_sync(0xffffffffu, g2, 16);
    g3 += __shfl_xor_sync(0xffffffffu, g3, 16);
    g4 += __shfl_xor_sync(0xffffffffu, g4, 16);
    g0 += b2[j];

    // layer-2 tanh jets + layer-3 partials (duplicated across k-half lanes;
    // halved by 0.5f before the full-warp reduce)
    float t, s;
    tanh_pair(g0, t, s);
    float t2 = t * t;
    float f2 = -2.0f * t * s;
    float f3 = 2.0f * s * fmaf(2.0f, t2, -s);
    float f4 = 8.0f * t * s * fmaf(-1.0f, t2, 2.0f * s);

    float g1sq = g1 * g1;
    float y1 = s * g1;
    float y2 = fmaf(s, g2, f2 * g1sq);
    float y3 = fmaf(s, g3, fmaf(3.0f * f2 * g1, g2, f3 * g1sq * g1));
    float y4 = fmaf(s, g4,
               fmaf(f2, fmaf(4.0f * g1, g3, 3.0f * g2 * g2),
               fmaf(6.0f * f3 * g1sq, g2, f4 * g1sq * g1sq)));

    float wu = 0.5f * W3[j];
    float ww = 0.5f * W3[16 + j];
    float u0 = wu * t,  u1 = wu * y1, u2 = wu * y2;
    float w0 = ww * t,  w1 = ww * y1;
    float w2a = ww * y2, w3a = ww * y3, w4a = ww * y4;

#define RED32(v) v += __shfl_xor_sync(0xffffffffu, v, 1); \
                 v += __shfl_xor_sync(0xffffffffu, v, 2); \
                 v += __shfl_xor_sync(0xffffffffu, v, 4); \
                 v += __shfl_xor_sync(0xffffffffu, v, 8); \
                 v += __shfl_xor_sync(0xffffffffu, v, 16);
    RED32(u0) RED32(u1) RED32(u2)
    RED32(w0) RED32(w1) RED32(w2a) RED32(w3a) RED32(w4a)
#undef RED32

    if (lane == 0) {
        u0 += b3[0];
        w0 += b3[1];
        const float h1f = hstep;
        const float h2f = hstep * hstep * 0.5f;
        const float h3f = hstep * hstep * hstep * (1.0f / 6.0f);
        const float h4f = hstep * hstep * hstep * hstep * (1.0f / 24.0f);
        g_tabA[node] = make_float4(u0, u1 * h1f, u2 * h2f, w4a * h4f);
        g_tabB[node] = make_float4(w0, w1 * h1f, w2a * h2f, w3a * h3f);
    }
}

__device__ __forceinline__ void eval_point(
    const float4* __restrict__ sA, const float4* __restrict__ sB, float z,
    float& u, float& w, float& wx, float& Nf, float& Mf, float& Qf)
{
    float f = z * FNODES;                       // exact (power-of-2 scale)
    int idx = __float2int_rn(f);
    idx = idx < 0 ? 0 : (idx > NODES ? NODES : idx);
    float t = f - (float)idx;                   // exact, in [-1/2, 1/2]

    float4 A = sA[idx];    // (U0, U1, U2, W4)
    float4 B = sB[idx];    // (W0, W1, W2, W3)

    u  = fmaf(t, fmaf(t, A.z, A.y), A.x);
    float up = FNODES * fmaf(t, A.z + A.z, A.y);
    w  = fmaf(t, fmaf(t, fmaf(t, fmaf(t, A.w, B.w), B.z), B.y), B.x);
    wx = FNODES * fmaf(t, fmaf(t, fmaf(t, 4.0f * A.w, 3.0f * B.w), B.z + B.z), B.y);
    float wpp = FN2 * fmaf(t, fmaf(t, 12.0f * A.w, 6.0f * B.w), B.z + B.z);
    float wppp = FN3 * fmaf(t, 24.0f * A.w, 6.0f * B.w);

    Nf = EA_C * fmaf(0.5f * wx, wx, up);
    Mf = -EI_C * wpp;
    Qf = fmaf(Nf, wx, -EI_C * wppp);
}

__global__ __launch_bounds__(CTA_THREADS, 3) void pinn_fused(
    const float* __restrict__ x,
    const float* __restrict__ W1, const float* __restrict__ b1,
    const float* __restrict__ W2, const float* __restrict__ b2,
    const float* __restrict__ W3, const float* __restrict__ b3,
    float* __restrict__ out, int n)
{
    __shared__ float4 sA[NNODES];   // 2,064 B
    __shared__ float4 sB[NNODES];   // 2,064 B

    int n2 = n >> 1;
    int tid = threadIdx.x;
    int q0 = blockIdx.x * CTA_THREADS + tid;
    const int gstride = GRID_CTAS * CTA_THREADS;

    // Prefetch this thread's x pairs while the table is being built.
    const float2* x2 = reinterpret_cast<const float2*>(x);
    float2 xs0 = make_float2(0.f, 0.f), xs1 = make_float2(0.f, 0.f);
    bool v0 = q0 < n2;
    int q1 = q0 + gstride;
    bool v1 = q1 < n2;
    if (v0) xs0 = x2[q0];
    if (v1) xs1 = x2[q1];

    // ---- phase 1: build (CTAs 0..128, warp 0 only) ----
    if (blockIdx.x < NNODES && tid < 32)
        build_node(blockIdx.x, tid, W1, b1, W2, b2, W3, b3);

    // ---- grid barrier: self-resetting ticket (monotonic counter) ----
    // Thread 0 is the table writer (lane 0) in build CTAs, so the
    // store -> threadfence -> atomicAdd publication chain is one thread.
    __syncthreads();
    if (tid == 0) {
        __threadfence();
        unsigned int pos = atomicAdd(&g_ticket, 1u);
        unsigned int target = (pos / GRID_CTAS + 1u) * GRID_CTAS;
        volatile unsigned int* tp = &g_ticket;
        while (*tp < target) __nanosleep(32);
        __threadfence();
    }
    __syncthreads();

    // ---- phase 2: table -> SMEM, evaluate ----
    if (tid < NNODES) {
        sA[tid] = g_tabA[tid];
        sB[tid] = g_tabB[tid];
    }
    __syncthreads();

    float2* o2 = reinterpret_cast<float2*>(out);
    if (v0) {
        float2 ru, rw, rwx, rN, rM, rQ;
        eval_point(sA, sB, xs0.x, ru.x, rw.x, rwx.x, rN.x, rM.x, rQ.x);
        eval_point(sA, sB, xs0.y, ru.y, rw.y, rwx.y, rN.y, rM.y, rQ.y);
        o2[0 * n2 + q0] = ru;
        o2[1 * n2 + q0] = rw;
        o2[2 * n2 + q0] = rwx;
        o2[3 * n2 + q0] = rN;
        o2[4 * n2 + q0] = rM;
        o2[5 * n2 + q0] = rQ;
    }
    if (v1) {
        float2 ru, rw, rwx, rN, rM, rQ;
        eval_point(sA, sB, xs1.x, ru.x, rw.x, rwx.x, rN.x, rM.x, rQ.x);
        eval_point(sA, sB, xs1.y, ru.y, rw.y, rwx.y, rN.y, rM.y, rQ.y);
        o2[0 * n2 + q1] = ru;
        o2[1 * n2 + q1] = rw;
        o2[2 * n2 + q1] = rwx;
        o2[3 * n2 + q1] = rN;
        o2[4 * n2 + q1] = rM;
        o2[5 * n2 + q1] = rQ;
    }
}

extern "C" void kernel_launch(void* const* d_in, const int* in_sizes, int n_in,
                              void* d_out, int out_size)
{
    const float* x  = (const float*)d_in[0];
    const float* W1 = (const float*)d_in[1];
    const float* b1 = (const float*)d_in[2];
    const float* W2 = (const float*)d_in[3];
    const float* b2 = (const float*)d_in[4];
    const float* W3 = (const float*)d_in[5];
    const float* b3 = (const float*)d_in[6];
    float* out = (float*)d_out;
    int n = in_sizes[0];

    pinn_fused<<<GRID_CTAS, CTA_THREADS>>>(x, W1, b1, W2, b2, W3, b3, out, n);
}